// round 10
// baseline (speedup 1.0000x reference)
#include <cuda_runtime.h>
#include <cuda_bf16.h>
#include <cstdint>

#define BMAX 8192
#define TILE 128
#define SK   32                        // screen dims (K=32: pass prob ~5e-14)
#define LDSB 40                        // smem stride (bf16) = 80B
#define AB_BYTES (TILE * LDSB * 2)     // 10240 B per operand tile
#define STAGE_B  (2 * AB_BYTES + 1024) // A + B + pI(512B) + pJ(512B) = 21504
#define NSCTA 296
#define PREPB 256

// Scratch (allocation-free rule: __device__ globals). Overwritten each replay;
// g_corr/g_done statically 0 and self-reset by the finalizer.
__device__ __align__(16) __nv_bfloat16 g_x32[BMAX * SK];
__device__ float  g_rs[BMAX];          // row sum (fp32)
__device__ float  g_sqn[BMAX];         // row squared norm
__device__ float  g_p[BMAX];           // (n32 - 2) / 2 (screen threshold term)
__device__ int    g_lab[BMAX];
__device__ float  g_Spart[PREPB][512]; // per-block per-class vector sums
__device__ double g_Qpart[PREPB][2];   // per-block per-class sum of sq norms
__device__ double g_closed;            // closed-form sum (plain store)
__device__ double g_corr;              // correction accumulator (atomic)
__device__ int    g_done;

// ---------------- prep: 256 blocks x 256, warp-per-row (4 rows/warp) ---------
__global__ __launch_bounds__(256) void prep_kernel(const float* __restrict__ x,
                                                   const int* __restrict__ lab32,
                                                   int B, int D) {
    const int t = threadIdx.x, warp = t >> 5, lane = t & 31, blk = blockIdx.x;
    __shared__ int s_any;
    __shared__ float sS[512];
    __shared__ double sQ[2];
    if (t == 0) s_any = 0;
    if (t < 2) sQ[t] = 0.0;
    for (int i = t; i < 512; i += 256) sS[i] = 0.f;
    __syncthreads();

    // label dtype detect on a 1024-pair prefix (int64 -> odd words all zero)
    {
        int any = 0;
        const int2* l2 = (const int2*)lab32;
        int lim = (B / 2 < 1024) ? B / 2 : 1024;
        for (int k = t; k < lim; k += 256) any |= l2[k].y;
        if (any) atomicOr(&s_any, 1);
    }
    __syncthreads();
    const int is32 = (s_any != 0);

    float sc0[8] = {0,0,0,0,0,0,0,0};
    float sc1[8] = {0,0,0,0,0,0,0,0};

    for (int row = blk * 8 + warp; row < B; row += PREPB * 8) {
        const float* xr = x + (size_t)row * D;
        float4 v0 = *reinterpret_cast<const float4*>(xr + lane * 8);
        float4 v1 = *reinterpret_cast<const float4*>(xr + lane * 8 + 4);
        float v[8] = {v0.x, v0.y, v0.z, v0.w, v1.x, v1.y, v1.z, v1.w};
        float s = 0.f, ss = 0.f;
        #pragma unroll
        for (int k = 0; k < 8; k++) { s += v[k]; ss += v[k] * v[k]; }
        float ss32 = (lane < 4) ? ss : 0.f;   // dims [0,32)

        const int labr = is32 ? lab32[row] : lab32[2 * row];

        if (lane < 4) {   // bf16 screen vector for dims [0,32)
            __nv_bfloat162 p0 = __floats2bfloat162_rn(v[0], v[1]);
            __nv_bfloat162 p1 = __floats2bfloat162_rn(v[2], v[3]);
            __nv_bfloat162 p2 = __floats2bfloat162_rn(v[4], v[5]);
            __nv_bfloat162 p3 = __floats2bfloat162_rn(v[6], v[7]);
            uint4 pk;
            pk.x = *reinterpret_cast<uint32_t*>(&p0);
            pk.y = *reinterpret_cast<uint32_t*>(&p1);
            pk.z = *reinterpret_cast<uint32_t*>(&p2);
            pk.w = *reinterpret_cast<uint32_t*>(&p3);
            *reinterpret_cast<uint4*>(&g_x32[(size_t)row * SK + lane * 8]) = pk;
        }

        if (labr != 0) {
            #pragma unroll
            for (int k = 0; k < 8; k++) sc1[k] += v[k];
        } else {
            #pragma unroll
            for (int k = 0; k < 8; k++) sc0[k] += v[k];
        }

        #pragma unroll
        for (int o = 16; o > 0; o >>= 1) {
            s    += __shfl_down_sync(0xffffffffu, s,    o);
            ss   += __shfl_down_sync(0xffffffffu, ss,   o);
            ss32 += __shfl_down_sync(0xffffffffu, ss32, o);
        }
        if (lane == 0) {
            g_lab[row] = labr;
            g_rs[row]  = s;
            g_sqn[row] = ss;
            g_p[row]   = (ss32 - 2.0f) * 0.5f;
            atomicAdd(&sQ[labr != 0 ? 1 : 0], (double)ss);
        }
    }

    #pragma unroll
    for (int k = 0; k < 8; k++) {
        atomicAdd(&sS[lane * 8 + k],       sc0[k]);
        atomicAdd(&sS[256 + lane * 8 + k], sc1[k]);
    }
    __syncthreads();
    for (int i = t; i < 512; i += 256) g_Spart[blk][i] = sS[i];
    if (t < 2) g_Qpart[blk][t] = sQ[t];
}

// ---------------- exact correction (cold path; i < j guaranteed) -------------
__device__ __noinline__ void correction(const float* __restrict__ x,
                                        int i, int j, int D) {
    const float* xi = x + (size_t)i * D;
    const float* xj = x + (size_t)j * D;
    double d0 = 0.0, d1 = 0.0, d2 = 0.0, d3 = 0.0;
    for (int d = 0; d < D; d += 4) {
        float4 a = *reinterpret_cast<const float4*>(xi + d);
        float4 b = *reinterpret_cast<const float4*>(xj + d);
        d0 += (double)a.x * b.x;
        d1 += (double)a.y * b.y;
        d2 += (double)a.z * b.z;
        d3 += (double)a.w * b.w;
    }
    double dot = (d0 + d1) + (d2 + d3);
    const float EPS = 1e-6f;
    float sq = (float)((double)g_sqn[i] + (double)g_sqn[j] - 2.0 * dot)
             + 2.0f * EPS * (g_rs[i] - g_rs[j]) + (float)D * EPS * EPS;
    bool same = (g_lab[i] == g_lab[j]);
    float assumed = same ? sq : 0.0f;
    float truev;
    if (same) {
        truev = fmaxf(sq, 1e-12f);
    } else {
        float dd = sqrtf(fmaxf(sq, 1e-12f));
        float tt = fmaxf(1.0f - dd, 0.0f);
        truev = tt * tt;
    }
    if (truev != assumed) atomicAdd(&g_corr, (double)(truev - assumed));
}

__device__ __forceinline__ uint32_t smem_u32(const void* p) {
    return (uint32_t)__cvta_generic_to_shared(p);
}

// closed-form triangle decode: C(i) = i*(NT-1) - i*(i-1)/2
__device__ __forceinline__ int tri_cum(int a, int NT) {
    return a * (NT - 1) - (a * (a - 1)) / 2;
}
__device__ __forceinline__ void tile_map(int p, int NT, int offdiag,
                                         int& ti, int& tj, bool& dg) {
    if (p < offdiag) {
        float tf = (float)(2 * NT - 1);
        int i = (int)((tf - sqrtf(fmaxf(tf * tf - 8.0f * (float)p, 0.f))) * 0.5f);
        if (i < 0) i = 0;
        if (i > NT - 2) i = NT - 2;
        while (i < NT - 2 && tri_cum(i + 1, NT) <= p) i++;
        while (i > 0 && tri_cum(i, NT) > p) i--;
        ti = i; tj = i + 1 + (p - tri_cum(i, NT)); dg = false;
    } else {
        ti = tj = p - offdiag; dg = true;
    }
}

// stage one tile (A rows r0.., B rows c0.., 32 bf16 each) + thresholds
__device__ __forceinline__ void stage_tile(uint32_t sb, int r0, int c0, int tid) {
    const int row = tid >> 2, q = tid & 3;
    #pragma unroll
    for (int it = 0; it < 2; it++) {
        int r = row + 64 * it;
        uint32_t da = sb + (uint32_t)(r * 80 + q * 16);
        const void* ga = &g_x32[(size_t)(r0 + r) * SK + q * 8];
        asm volatile("cp.async.ca.shared.global [%0], [%1], 16;" :: "r"(da), "l"(ga));
        uint32_t db = da + (uint32_t)AB_BYTES;
        const void* gb = &g_x32[(size_t)(c0 + r) * SK + q * 8];
        asm volatile("cp.async.ca.shared.global [%0], [%1], 16;" :: "r"(db), "l"(gb));
    }
    if (tid < 32) {
        uint32_t dp = sb + 2u * AB_BYTES + (uint32_t)tid * 16u;
        const void* gp = &g_p[r0 + tid * 4];
        asm volatile("cp.async.ca.shared.global [%0], [%1], 16;" :: "r"(dp), "l"(gp));
    } else if (tid < 64) {
        uint32_t dp = sb + 2u * AB_BYTES + 512u + (uint32_t)(tid - 32) * 16u;
        const void* gp = &g_p[c0 + (tid - 32) * 4];
        asm volatile("cp.async.ca.shared.global [%0], [%1], 16;" :: "r"(dp), "l"(gp));
    }
    asm volatile("cp.async.commit_group;");
}

// ---------------- persistent screen + fused closed form + finalize -----------
__global__ __launch_bounds__(256, 2) void screen_kernel(const float* __restrict__ x,
                                                        float* __restrict__ out,
                                                        int B, int D, int NT,
                                                        int offdiag, int total,
                                                        double inv) {
    extern __shared__ __align__(16) char dyn[];
    const uint32_t base = smem_u32(dyn);

    const int tid  = threadIdx.x;
    const int warp = tid >> 5;
    const int lane = tid & 31;
    const int grp  = lane >> 2;
    const int tg   = lane & 3;
    const int wm   = warp >> 2;
    const int wn   = warp & 3;

    // reversed tile base: block 0 (runs the closed phase too) gets fewest tiles
    const int pb = (int)gridDim.x - 1 - (int)blockIdx.x;

    // prologue: stage first tile
    {
        int ti, tj; bool dg;
        tile_map(pb, NT, offdiag, ti, tj, dg);
        stage_tile(base, ti * TILE, tj * TILE, tid);
    }

    // ---- closed-form phase (block 0 only; overlaps other CTAs' tiles) ----
    if (blockIdx.x == 0) {
        __shared__ int wsum[8];
        __shared__ double dred[4][8];
        const int bse = tid * 32;
        uint32_t bits = 0;
        int cnt = 0;
        #pragma unroll 4
        for (int k = 0; k < 32; k++) {
            int c = (bse + k < B && g_lab[bse + k] != 0) ? 1 : 0;
            bits |= (uint32_t)c << k;
            cnt += c;
        }
        int incl = cnt;
        #pragma unroll
        for (int o = 1; o < 32; o <<= 1) {
            int v = __shfl_up_sync(0xffffffffu, incl, o);
            if (lane >= o) incl += v;
        }
        if (lane == 31) wsum[warp] = incl;
        __syncthreads();
        int woff = 0, n1 = 0;
        #pragma unroll
        for (int w = 0; w < 8; w++) {
            if (w < warp) woff += wsum[w];
            n1 += wsum[w];
        }
        const int n0 = B - n1;
        int run1 = woff + incl - cnt;

        double R = 0.0;
        #pragma unroll 4
        for (int k = 0; k < 32; k++) {
            int i = bse + k;
            if (i >= B) break;
            int c = (bits >> k) & 1;
            int rank = c ? run1 : (i - run1);
            run1 += c;
            int nc = c ? n1 : n0;
            R += (double)g_rs[i] * (double)(nc - 1 - 2 * rank);
        }
        double sv0 = 0.0, sv1 = 0.0;
        for (int b = 0; b < PREPB; b++) {
            sv0 += (double)g_Spart[b][tid];
            sv1 += (double)g_Spart[b][256 + tid];
        }
        double s2 = sv0 * sv0 + sv1 * sv1;
        double q0 = g_Qpart[tid][0];
        double q1 = g_Qpart[tid][1];

        double vals[4] = { R, s2, q0, q1 };
        #pragma unroll
        for (int m = 0; m < 4; m++) {
            double v = vals[m];
            #pragma unroll
            for (int o = 16; o > 0; o >>= 1)
                v += __shfl_down_sync(0xffffffffu, v, o);
            if (lane == 0) dred[m][warp] = v;
        }
        __syncthreads();
        if (tid == 0) {
            double Rt = 0, S2 = 0, Q0 = 0, Q1 = 0;
            #pragma unroll
            for (int w = 0; w < 8; w++) {
                Rt += dred[0][w]; S2 += dred[1][w];
                Q0 += dred[2][w]; Q1 += dred[3][w];
            }
            const double EPS = 1e-6;
            double npairs = 0.5 * ((double)n0 * (n0 - 1) + (double)n1 * (n1 - 1));
            g_closed = (double)n0 * Q0 + (double)n1 * Q1 - S2
                     + 2.0 * EPS * Rt + (double)D * EPS * EPS * npairs;
        }
        __syncthreads();
    }

    // ---- ldmatrix offsets (within a stage buffer) ----
    const int rowA = wm * 64 + (lane & 15);
    const int aSel = (lane >> 4) * 8;
    const uint32_t aOff = (uint32_t)(rowA * LDSB + aSel) * 2u;
    const int colB = wn * 32 + ((lane >> 4) << 3) + (lane & 7);
    const int bSel = ((lane >> 3) & 1) * 8;
    const uint32_t bOff = (uint32_t)AB_BYTES + (uint32_t)(colB * LDSB + bSel) * 2u;

    int iL[8], jL[8];
    #pragma unroll
    for (int mt = 0; mt < 4; mt++) {
        iL[mt * 2]     = wm * 64 + mt * 16 + grp;
        iL[mt * 2 + 1] = iL[mt * 2] + 8;
    }
    #pragma unroll
    for (int nt = 0; nt < 4; nt++) {
        jL[nt * 2]     = wn * 32 + nt * 8 + tg * 2;
        jL[nt * 2 + 1] = jL[nt * 2] + 1;
    }

    int k = 0;
    for (int p = pb; p < total; p += gridDim.x, k++) {
        const int pn = p + gridDim.x;
        if (pn < total) {
            int ti, tj; bool dg;
            tile_map(pn, NT, offdiag, ti, tj, dg);
            stage_tile(base + (uint32_t)((k + 1) & 1) * STAGE_B,
                       ti * TILE, tj * TILE, tid);
            asm volatile("cp.async.wait_group 1;");
        } else {
            asm volatile("cp.async.wait_group 0;");
        }
        __syncthreads();

        int ti, tj; bool isDiag;
        tile_map(p, NT, offdiag, ti, tj, isDiag);
        const int r0 = ti * TILE, c0 = tj * TILE;
        const uint32_t sb = base + (uint32_t)(k & 1) * STAGE_B;

        float acc[4][4][4];
        #pragma unroll
        for (int a = 0; a < 4; a++)
            #pragma unroll
            for (int b = 0; b < 4; b++)
                #pragma unroll
                for (int c = 0; c < 4; c++) acc[a][b][c] = 0.f;

        #pragma unroll
        for (int ks = 0; ks < 2; ks++) {
            uint32_t af[4][4];
            #pragma unroll
            for (int mt = 0; mt < 4; mt++) {
                uint32_t addr = sb + aOff + (uint32_t)(mt * 16 * LDSB) * 2u
                              + (uint32_t)ks * 32u;
                asm volatile("ldmatrix.sync.aligned.m8n8.x4.shared.b16 {%0,%1,%2,%3}, [%4];\n"
                             : "=r"(af[mt][0]), "=r"(af[mt][1]), "=r"(af[mt][2]), "=r"(af[mt][3])
                             : "r"(addr));
            }
            uint32_t bfm[4][2];
            #pragma unroll
            for (int np = 0; np < 2; np++) {
                uint32_t addr = sb + bOff + (uint32_t)(np * 16 * LDSB) * 2u
                              + (uint32_t)ks * 32u;
                asm volatile("ldmatrix.sync.aligned.m8n8.x4.shared.b16 {%0,%1,%2,%3}, [%4];\n"
                             : "=r"(bfm[2 * np][0]), "=r"(bfm[2 * np][1]),
                               "=r"(bfm[2 * np + 1][0]), "=r"(bfm[2 * np + 1][1])
                             : "r"(addr));
            }
            #pragma unroll
            for (int mt = 0; mt < 4; mt++)
                #pragma unroll
                for (int nt = 0; nt < 4; nt++) {
                    float* d = acc[mt][nt];
                    asm volatile(
                        "mma.sync.aligned.m16n8k16.row.col.f32.bf16.bf16.f32 "
                        "{%0,%1,%2,%3}, {%4,%5,%6,%7}, {%8,%9}, {%0,%1,%2,%3};\n"
                        : "+f"(d[0]), "+f"(d[1]), "+f"(d[2]), "+f"(d[3])
                        : "r"(af[mt][0]), "r"(af[mt][1]), "r"(af[mt][2]), "r"(af[mt][3]),
                          "r"(bfm[nt][0]), "r"(bfm[nt][1]));
                }
        }

        const float* sPI = reinterpret_cast<const float*>(dyn + (size_t)(k & 1) * STAGE_B
                                                              + 2 * AB_BYTES);
        const float* sPJ = sPI + 128;
        float pI[8], pJ[8];
        #pragma unroll
        for (int u = 0; u < 8; u++) { pI[u] = sPI[iL[u]]; pJ[u] = sPJ[jL[u]]; }

        // branch-free screen: violation max m = max(g - pI - pJ); fires iff
        // some pair has sq32 < 4 (prob ~5e-14/pair). Diag: mask j<=i pairs.
        float m = -1.0f;
        if (!isDiag) {
            #pragma unroll
            for (int mt = 0; mt < 4; mt++)
                #pragma unroll
                for (int nt = 0; nt < 4; nt++)
                    #pragma unroll
                    for (int h = 0; h < 4; h++) {
                        int ui = mt * 2 + (h >> 1);
                        int uj = nt * 2 + (h & 1);
                        m = fmaxf(m, acc[mt][nt][h] - (pI[ui] + pJ[uj]));
                    }
        } else {
            #pragma unroll
            for (int mt = 0; mt < 4; mt++)
                #pragma unroll
                for (int nt = 0; nt < 4; nt++)
                    #pragma unroll
                    for (int h = 0; h < 4; h++) {
                        int ui = mt * 2 + (h >> 1);
                        int uj = nt * 2 + (h & 1);
                        float d = acc[mt][nt][h] - (pI[ui] + pJ[uj]);
                        m = fmaxf(m, (jL[uj] > iL[ui]) ? d : -1e30f);
                    }
        }

        // one barrier per tile: (a) block-wide fired flag, (b) buffer-reuse sync
        if (__syncthreads_or(m > 0.0f)) {
            // cold path (~never): exact per-pair corrections
            #pragma unroll 1
            for (int mt = 0; mt < 4; mt++)
                for (int nt = 0; nt < 4; nt++)
                    for (int h = 0; h < 4; h++) {
                        int ui = mt * 2 + (h >> 1);
                        int uj = nt * 2 + (h & 1);
                        if (acc[mt][nt][h] > pI[ui] + pJ[uj]) {
                            int i = r0 + iL[ui];
                            int j = c0 + jL[uj];
                            if (!isDiag || j > i) correction(x, i, j, D);
                        }
                    }
            __syncthreads();
        }
    }

    if (tid == 0) {
        __threadfence();
        int t = atomicAdd(&g_done, 1);
        if (t == (int)gridDim.x - 1) {
            g_done = 0;
            double v = g_closed + atomicAdd(&g_corr, 0.0);
            out[0] = (float)(v * inv);
            g_corr = 0.0;                 // reset for next replay
        }
    }
}

extern "C" void kernel_launch(void* const* d_in, const int* in_sizes, int n_in,
                              void* d_out, int out_size) {
    const float* x     = (const float*)d_in[0];
    const int*   lab32 = (const int*)d_in[1];
    int B = in_sizes[1];
    int D = in_sizes[0] / B;
    int NT = B / TILE;
    int offdiag = NT * (NT - 1) / 2;
    int total = offdiag + NT;
    int nblk = total < NSCTA ? total : NSCTA;
    double cnt = (double)B * (B - 1) / 2.0;
    double inv = 1.0 / (cnt + 1e-6);

    prep_kernel<<<PREPB, 256>>>(x, lab32, B, D);
    screen_kernel<<<nblk, 256, 2 * STAGE_B>>>(x, (float*)d_out, B, D, NT,
                                              offdiag, total, inv);
}

// round 11
// speedup vs baseline: 1.1895x; 1.1895x over previous
#include <cuda_runtime.h>
#include <cuda_bf16.h>
#include <cstdint>

#define BMAX 8192
#define TILE 128
#define SK   32                        // screen dims (K=32: pass prob ~5e-14)
#define STR  80                        // smem row stride bytes (conflict-free LDSM)
#define ABYTES (TILE * STR)            // 10240 B per operand tile
#define SMEM_PI  (5 * ABYTES)          // 51200
#define SMEM_PJ  (SMEM_PI + 512)       // 51712
#define SMEM_DYN (SMEM_PJ + 4 * 512)   // 53760
#define PREPB 256

// Scratch (allocation-free rule: __device__ globals). Overwritten each replay;
// g_corr/g_done statically 0 and self-reset by the finalizer.
__device__ __align__(16) __nv_bfloat16 g_x32[BMAX * SK];
__device__ float  g_rs[BMAX];          // row sum (fp32)
__device__ float  g_sqn[BMAX];         // row squared norm
__device__ float  g_p[BMAX];           // (n32 - 2) / 2 (screen threshold term)
__device__ int    g_lab[BMAX];
__device__ float  g_Spart[PREPB][512]; // per-block per-class vector sums
__device__ double g_Qpart[PREPB][2];   // per-block per-class sum of sq norms
__device__ double g_closed;            // closed-form sum (plain store)
__device__ double g_corr;              // correction accumulator (atomic)
__device__ int    g_done;

// ---------------- prep: 256 blocks x 256, warp-per-row (4 rows/warp) ---------
__global__ __launch_bounds__(256) void prep_kernel(const float* __restrict__ x,
                                                   const int* __restrict__ lab32,
                                                   int B, int D) {
    const int t = threadIdx.x, warp = t >> 5, lane = t & 31, blk = blockIdx.x;
    __shared__ int s_any;
    __shared__ float sS[512];
    __shared__ double sQ[2];
    if (t == 0) s_any = 0;
    if (t < 2) sQ[t] = 0.0;
    for (int i = t; i < 512; i += 256) sS[i] = 0.f;
    __syncthreads();

    // label dtype detect on a 1024-pair prefix (int64 -> odd words all zero)
    {
        int any = 0;
        const int2* l2 = (const int2*)lab32;
        int lim = (B / 2 < 1024) ? B / 2 : 1024;
        for (int k = t; k < lim; k += 256) any |= l2[k].y;
        if (any) atomicOr(&s_any, 1);
    }
    __syncthreads();
    const int is32 = (s_any != 0);

    float sc0[8] = {0,0,0,0,0,0,0,0};
    float sc1[8] = {0,0,0,0,0,0,0,0};

    for (int row = blk * 8 + warp; row < B; row += PREPB * 8) {
        const float* xr = x + (size_t)row * D;
        float4 v0 = *reinterpret_cast<const float4*>(xr + lane * 8);
        float4 v1 = *reinterpret_cast<const float4*>(xr + lane * 8 + 4);
        float v[8] = {v0.x, v0.y, v0.z, v0.w, v1.x, v1.y, v1.z, v1.w};
        float s = 0.f, ss = 0.f;
        #pragma unroll
        for (int k = 0; k < 8; k++) { s += v[k]; ss += v[k] * v[k]; }
        float ss32 = (lane < 4) ? ss : 0.f;   // dims [0,32)

        const int labr = is32 ? lab32[row] : lab32[2 * row];

        if (lane < 4) {   // bf16 screen vector for dims [0,32)
            __nv_bfloat162 p0 = __floats2bfloat162_rn(v[0], v[1]);
            __nv_bfloat162 p1 = __floats2bfloat162_rn(v[2], v[3]);
            __nv_bfloat162 p2 = __floats2bfloat162_rn(v[4], v[5]);
            __nv_bfloat162 p3 = __floats2bfloat162_rn(v[6], v[7]);
            uint4 pk;
            pk.x = *reinterpret_cast<uint32_t*>(&p0);
            pk.y = *reinterpret_cast<uint32_t*>(&p1);
            pk.z = *reinterpret_cast<uint32_t*>(&p2);
            pk.w = *reinterpret_cast<uint32_t*>(&p3);
            *reinterpret_cast<uint4*>(&g_x32[(size_t)row * SK + lane * 8]) = pk;
        }

        if (labr != 0) {
            #pragma unroll
            for (int k = 0; k < 8; k++) sc1[k] += v[k];
        } else {
            #pragma unroll
            for (int k = 0; k < 8; k++) sc0[k] += v[k];
        }

        #pragma unroll
        for (int o = 16; o > 0; o >>= 1) {
            s    += __shfl_down_sync(0xffffffffu, s,    o);
            ss   += __shfl_down_sync(0xffffffffu, ss,   o);
            ss32 += __shfl_down_sync(0xffffffffu, ss32, o);
        }
        if (lane == 0) {
            g_lab[row] = labr;
            g_rs[row]  = s;
            g_sqn[row] = ss;
            g_p[row]   = (ss32 - 2.0f) * 0.5f;
            atomicAdd(&sQ[labr != 0 ? 1 : 0], (double)ss);
        }
    }

    #pragma unroll
    for (int k = 0; k < 8; k++) {
        atomicAdd(&sS[lane * 8 + k],       sc0[k]);
        atomicAdd(&sS[256 + lane * 8 + k], sc1[k]);
    }
    __syncthreads();
    for (int i = t; i < 512; i += 256) g_Spart[blk][i] = sS[i];
    if (t < 2) g_Qpart[blk][t] = sQ[t];
}

// ---------------- exact correction (cold path; i < j guaranteed) -------------
__device__ __noinline__ void correction(const float* __restrict__ x,
                                        int i, int j, int D) {
    const float* xi = x + (size_t)i * D;
    const float* xj = x + (size_t)j * D;
    double d0 = 0.0, d1 = 0.0, d2 = 0.0, d3 = 0.0;
    for (int d = 0; d < D; d += 4) {
        float4 a = *reinterpret_cast<const float4*>(xi + d);
        float4 b = *reinterpret_cast<const float4*>(xj + d);
        d0 += (double)a.x * b.x;
        d1 += (double)a.y * b.y;
        d2 += (double)a.z * b.z;
        d3 += (double)a.w * b.w;
    }
    double dot = (d0 + d1) + (d2 + d3);
    const float EPS = 1e-6f;
    float sq = (float)((double)g_sqn[i] + (double)g_sqn[j] - 2.0 * dot)
             + 2.0f * EPS * (g_rs[i] - g_rs[j]) + (float)D * EPS * EPS;
    bool same = (g_lab[i] == g_lab[j]);
    float assumed = same ? sq : 0.0f;
    float truev;
    if (same) {
        truev = fmaxf(sq, 1e-12f);
    } else {
        float dd = sqrtf(fmaxf(sq, 1e-12f));
        float tt = fmaxf(1.0f - dd, 0.0f);
        truev = tt * tt;
    }
    if (truev != assumed) atomicAdd(&g_corr, (double)(truev - assumed));
}

__device__ __forceinline__ uint32_t smem_u32(const void* p) {
    return (uint32_t)__cvta_generic_to_shared(p);
}

// ---------------- strip screen: 128x512 per CTA, one barrier phase -----------
// block 0: closed-form only. blocks 1..: strip (ti, cs) covering column tiles
// tjs..tjs+3 (clipped), tjs = ti + 4*cs.
__global__ __launch_bounds__(256, 2) void screen_kernel(const float* __restrict__ x,
                                                        float* __restrict__ out,
                                                        int B, int D, int NT,
                                                        int SPR, double inv) {
    extern __shared__ __align__(16) char dyn[];
    const uint32_t base = smem_u32(dyn);

    const int tid  = threadIdx.x;
    const int warp = tid >> 5;
    const int lane = tid & 31;

    if (blockIdx.x == 0) {
        // ---- closed-form block ----
        __shared__ int wsum[8];
        __shared__ double dred[4][8];
        const int grp32 = tid * 32;
        uint32_t bits = 0;
        int cnt = 0;
        #pragma unroll 4
        for (int k = 0; k < 32; k++) {
            int c = (grp32 + k < B && g_lab[grp32 + k] != 0) ? 1 : 0;
            bits |= (uint32_t)c << k;
            cnt += c;
        }
        int incl = cnt;
        #pragma unroll
        for (int o = 1; o < 32; o <<= 1) {
            int v = __shfl_up_sync(0xffffffffu, incl, o);
            if (lane >= o) incl += v;
        }
        if (lane == 31) wsum[warp] = incl;
        __syncthreads();
        int woff = 0, n1 = 0;
        #pragma unroll
        for (int w = 0; w < 8; w++) {
            if (w < warp) woff += wsum[w];
            n1 += wsum[w];
        }
        const int n0 = B - n1;
        int run1 = woff + incl - cnt;

        double R = 0.0;
        #pragma unroll 4
        for (int k = 0; k < 32; k++) {
            int i = grp32 + k;
            if (i >= B) break;
            int c = (bits >> k) & 1;
            int rank = c ? run1 : (i - run1);
            run1 += c;
            int nc = c ? n1 : n0;
            R += (double)g_rs[i] * (double)(nc - 1 - 2 * rank);
        }
        double sv0 = 0.0, sv1 = 0.0;
        for (int b = 0; b < PREPB; b++) {
            sv0 += (double)g_Spart[b][tid];
            sv1 += (double)g_Spart[b][256 + tid];
        }
        double s2 = sv0 * sv0 + sv1 * sv1;
        double q0 = g_Qpart[tid][0];
        double q1 = g_Qpart[tid][1];

        double vals[4] = { R, s2, q0, q1 };
        #pragma unroll
        for (int m2 = 0; m2 < 4; m2++) {
            double v = vals[m2];
            #pragma unroll
            for (int o = 16; o > 0; o >>= 1)
                v += __shfl_down_sync(0xffffffffu, v, o);
            if (lane == 0) dred[m2][warp] = v;
        }
        __syncthreads();
        if (tid == 0) {
            double Rt = 0, S2 = 0, Q0 = 0, Q1 = 0;
            #pragma unroll
            for (int w = 0; w < 8; w++) {
                Rt += dred[0][w]; S2 += dred[1][w];
                Q0 += dred[2][w]; Q1 += dred[3][w];
            }
            const double EPS = 1e-6;
            double npairs = 0.5 * ((double)n0 * (n0 - 1) + (double)n1 * (n1 - 1));
            g_closed = (double)n0 * Q0 + (double)n1 * Q1 - S2
                     + 2.0 * EPS * Rt + (double)D * EPS * EPS * npairs;
        }
    } else {
        const int w = (int)blockIdx.x - 1;
        const int ti  = w / SPR;
        const int cs  = w - ti * SPR;
        const int tjs = ti + 4 * cs;
        if (tjs < NT) {
            const int nTiles = (NT - tjs < 4) ? (NT - tjs) : 4;
            const int r0 = ti * TILE;

            // ---- stage: A, B[0..nTiles), thresholds; one commit ----
            for (int idx = tid; idx < 512; idx += 256) {
                int row = idx >> 2, q = idx & 3;
                uint32_t da = base + (uint32_t)(row * STR + q * 16);
                const void* ga = &g_x32[(size_t)(r0 + row) * SK + q * 8];
                asm volatile("cp.async.ca.shared.global [%0], [%1], 16;" :: "r"(da), "l"(ga));
            }
            for (int nt = 0; nt < nTiles; nt++) {
                int c0 = (tjs + nt) * TILE;
                uint32_t bb = base + (uint32_t)((1 + nt) * ABYTES);
                for (int idx = tid; idx < 512; idx += 256) {
                    int row = idx >> 2, q = idx & 3;
                    uint32_t db = bb + (uint32_t)(row * STR + q * 16);
                    const void* gb = &g_x32[(size_t)(c0 + row) * SK + q * 8];
                    asm volatile("cp.async.ca.shared.global [%0], [%1], 16;" :: "r"(db), "l"(gb));
                }
                if (tid < 32) {
                    uint32_t dp = base + (uint32_t)(SMEM_PJ + nt * 512 + tid * 16);
                    const void* gp = &g_p[c0 + tid * 4];
                    asm volatile("cp.async.ca.shared.global [%0], [%1], 16;" :: "r"(dp), "l"(gp));
                }
            }
            if (tid < 32) {
                uint32_t dp = base + (uint32_t)(SMEM_PI + tid * 16);
                const void* gp = &g_p[r0 + tid * 4];
                asm volatile("cp.async.ca.shared.global [%0], [%1], 16;" :: "r"(dp), "l"(gp));
            }
            asm volatile("cp.async.commit_group;");
            asm volatile("cp.async.wait_group 0;");
            __syncthreads();

            // ---- compute: 4 tiles, no barriers between ----
            const int grp = lane >> 2;
            const int tg  = lane & 3;
            const int wm  = warp >> 2;
            const int wn  = warp & 3;

            const int rowA = wm * 64 + (lane & 15);
            const uint32_t aOff = (uint32_t)(rowA * STR + ((lane >> 4) * 8) * 2);
            const int colB = wn * 32 + ((lane >> 4) << 3) + (lane & 7);
            const uint32_t bOff = (uint32_t)(colB * STR + (((lane >> 3) & 1) * 8) * 2);

            int iL[8], jL[8];
            #pragma unroll
            for (int mt = 0; mt < 4; mt++) {
                iL[mt * 2]     = wm * 64 + mt * 16 + grp;
                iL[mt * 2 + 1] = iL[mt * 2] + 8;
            }
            #pragma unroll
            for (int nt = 0; nt < 4; nt++) {
                jL[nt * 2]     = wn * 32 + nt * 8 + tg * 2;
                jL[nt * 2 + 1] = jL[nt * 2] + 1;
            }
            const float* sPI = reinterpret_cast<const float*>(dyn + SMEM_PI);
            float pI[8];
            #pragma unroll
            for (int u = 0; u < 8; u++) pI[u] = sPI[iL[u]];

            float m = -1e30f;
            for (int nt = 0; nt < nTiles; nt++) {
                const uint32_t sbB = base + (uint32_t)((1 + nt) * ABYTES);
                float acc[4][4][4];
                #pragma unroll
                for (int a = 0; a < 4; a++)
                    #pragma unroll
                    for (int b = 0; b < 4; b++)
                        #pragma unroll
                        for (int c = 0; c < 4; c++) acc[a][b][c] = 0.f;

                #pragma unroll
                for (int ks = 0; ks < 2; ks++) {
                    uint32_t af[4][4];
                    #pragma unroll
                    for (int mt = 0; mt < 4; mt++) {
                        uint32_t addr = base + aOff + (uint32_t)(mt * 16 * STR)
                                      + (uint32_t)ks * 32u;
                        asm volatile("ldmatrix.sync.aligned.m8n8.x4.shared.b16 {%0,%1,%2,%3}, [%4];\n"
                                     : "=r"(af[mt][0]), "=r"(af[mt][1]),
                                       "=r"(af[mt][2]), "=r"(af[mt][3])
                                     : "r"(addr));
                    }
                    uint32_t bfm[4][2];
                    #pragma unroll
                    for (int np = 0; np < 2; np++) {
                        uint32_t addr = sbB + bOff + (uint32_t)(np * 16 * STR)
                                      + (uint32_t)ks * 32u;
                        asm volatile("ldmatrix.sync.aligned.m8n8.x4.shared.b16 {%0,%1,%2,%3}, [%4];\n"
                                     : "=r"(bfm[2 * np][0]), "=r"(bfm[2 * np][1]),
                                       "=r"(bfm[2 * np + 1][0]), "=r"(bfm[2 * np + 1][1])
                                     : "r"(addr));
                    }
                    #pragma unroll
                    for (int mt = 0; mt < 4; mt++)
                        #pragma unroll
                        for (int nt2 = 0; nt2 < 4; nt2++) {
                            float* d = acc[mt][nt2];
                            asm volatile(
                                "mma.sync.aligned.m16n8k16.row.col.f32.bf16.bf16.f32 "
                                "{%0,%1,%2,%3}, {%4,%5,%6,%7}, {%8,%9}, {%0,%1,%2,%3};\n"
                                : "+f"(d[0]), "+f"(d[1]), "+f"(d[2]), "+f"(d[3])
                                : "r"(af[mt][0]), "r"(af[mt][1]), "r"(af[mt][2]), "r"(af[mt][3]),
                                  "r"(bfm[nt2][0]), "r"(bfm[nt2][1]));
                        }
                }

                const float* sPJ = reinterpret_cast<const float*>(dyn + SMEM_PJ + nt * 512);
                float pJ[8];
                #pragma unroll
                for (int u = 0; u < 8; u++) pJ[u] = sPJ[jL[u]];

                const bool diag = (tjs + nt == ti);
                if (!diag) {
                    #pragma unroll
                    for (int mt = 0; mt < 4; mt++)
                        #pragma unroll
                        for (int nt2 = 0; nt2 < 4; nt2++)
                            #pragma unroll
                            for (int h = 0; h < 4; h++) {
                                int ui = mt * 2 + (h >> 1);
                                int uj = nt2 * 2 + (h & 1);
                                m = fmaxf(m, acc[mt][nt2][h] - (pI[ui] + pJ[uj]));
                            }
                } else {
                    #pragma unroll
                    for (int mt = 0; mt < 4; mt++)
                        #pragma unroll
                        for (int nt2 = 0; nt2 < 4; nt2++)
                            #pragma unroll
                            for (int h = 0; h < 4; h++) {
                                int ui = mt * 2 + (h >> 1);
                                int uj = nt2 * 2 + (h & 1);
                                float d = acc[mt][nt2][h] - (pI[ui] + pJ[uj]);
                                m = fmaxf(m, (jL[uj] > iL[ui]) ? d : -1e30f);
                            }
                }
            }

            // ---- cold path (~never): scalar re-screen from smem ----
            if (__syncthreads_or(m > 0.0f)) {
                for (int nt = 0; nt < nTiles; nt++) {
                    const bool diag = (tjs + nt == ti);
                    const int c0 = (tjs + nt) * TILE;
                    const char* bA = dyn;
                    const char* bB = dyn + (1 + nt) * ABYTES;
                    for (int idx = tid; idx < TILE * TILE; idx += 256) {
                        int i = idx >> 7, j = idx & 127;
                        if (diag && j <= i) continue;
                        float sq32 = 0.f;
                        for (int d = 0; d < SK; d++) {
                            float a = __bfloat162float(
                                *reinterpret_cast<const __nv_bfloat16*>(bA + i * STR + d * 2));
                            float b = __bfloat162float(
                                *reinterpret_cast<const __nv_bfloat16*>(bB + j * STR + d * 2));
                            float df = a - b;
                            sq32 += df * df;
                        }
                        if (sq32 < 4.0f) correction(x, r0 + i, c0 + j, D);
                    }
                }
            }
        }
    }

    if (tid == 0) {
        __threadfence();
        int t = atomicAdd(&g_done, 1);
        if (t == (int)gridDim.x - 1) {
            g_done = 0;
            double v = g_closed + atomicAdd(&g_corr, 0.0);
            out[0] = (float)(v * inv);
            g_corr = 0.0;                 // reset for next replay
        }
    }
}

extern "C" void kernel_launch(void* const* d_in, const int* in_sizes, int n_in,
                              void* d_out, int out_size) {
    const float* x     = (const float*)d_in[0];
    const int*   lab32 = (const int*)d_in[1];
    int B = in_sizes[1];
    int D = in_sizes[0] / B;
    int NT = B / TILE;
    int SPR = (NT + 3) / 4;
    int grid = 1 + NT * SPR;
    double cnt = (double)B * (B - 1) / 2.0;
    double inv = 1.0 / (cnt + 1e-6);

    cudaFuncSetAttribute(screen_kernel,
                         cudaFuncAttributeMaxDynamicSharedMemorySize, SMEM_DYN);

    prep_kernel<<<PREPB, 256>>>(x, lab32, B, D);
    screen_kernel<<<grid, 256, SMEM_DYN>>>(x, (float*)d_out, B, D, NT, SPR, inv);
}